// round 5
// baseline (speedup 1.0000x reference)
#include <cuda_runtime.h>
#include <cstdint>

#define B_ 8
#define C_ 16
#define H_ 224
#define W_ 224
#define T_ 8
#define N_ 5
#define NEGV (-1e30f)
#define NTOT (B_*C_*H_*W_)
#define FULLM 0xffffffffu

// Scratch: xv = log1p(relu(x)); padded so block prefetch can't run off the end.
__device__ float g_xv[NTOT + 4 * W_];

__global__ void xv_kernel(const float* __restrict__ x) {
    int n4 = NTOT / 4;
    for (int i = blockIdx.x * blockDim.x + threadIdx.x; i < n4;
         i += gridDim.x * blockDim.x) {
        float4 v = reinterpret_cast<const float4*>(x)[i];
        v.x = log1pf(fmaxf(v.x, 0.f));
        v.y = log1pf(fmaxf(v.y, 0.f));
        v.z = log1pf(fmaxf(v.z, 0.f));
        v.w = log1pf(fmaxf(v.w, 0.f));
        reinterpret_cast<float4*>(g_xv)[i] = v;
    }
}

struct Forest { int par[T_][N_]; };

union F2U { float2 f; unsigned long long u; };
__device__ __forceinline__ float2 f2add(float2 a, float2 b) {
    F2U A, B, R; A.f = a; B.f = b;
    asm("add.rn.f32x2 %0, %1, %2;" : "=l"(R.u) : "l"(A.u), "l"(B.u));
    return R.f;
}

// acc[r] = xv[r] + a (broadcast), 4 rows, packed adds.
__device__ __forceinline__ void build_acc(float acc[4][8], const float xv[4][8],
                                          float2 a) {
#pragma unroll
    for (int r = 0; r < 4; r++) {
        const float2* s = reinterpret_cast<const float2*>(xv[r]);
        float2* d = reinterpret_cast<float2*>(acc[r]);
#pragma unroll
        for (int k = 0; k < 4; k++) d[k] = f2add(s[k], a);
    }
}

// acc_row[w] += S[w-1]  (shifted by one column; NEGV boundary at col 0)
__device__ __forceinline__ void add_shift_row(float accr[8], const float S[8],
                                              int lane) {
    float bnd = __shfl_up_sync(FULLM, S[7], 1);
    if (lane == 0) bnd = NEGV;
    accr[0] += bnd;
#pragma unroll
    for (int k = 1; k < 8; k++) accr[k] += S[k - 1];
}

// Add child state (rows -1..2 => oldM, r[0], r[1], r[2]) shifted into acc rows 0..3.
__device__ __forceinline__ void add_shift(float acc[4][8], const float oldM[8],
                                          const float r[4][8], int lane) {
    add_shift_row(acc[0], oldM, lane);
    add_shift_row(acc[1], r[0], lane);
    add_shift_row(acc[2], r[1], lane);
    add_shift_row(acc[3], r[2], lane);
}

// Scan 4 independent rows (acc), merge with running M (old, NOT modified),
// produce per-row inclusive 2D-cummax states rr[0..3] (rr[3] = new M).
// The 4 warp-scan chains are interleaved -> structural ILP.
__device__ __forceinline__ void scan_block(float acc[4][8], const float M[8],
                                           float rr[4][8], int lane) {
    // chunk prefix per row
#pragma unroll
    for (int r = 0; r < 4; r++)
#pragma unroll
        for (int k = 1; k < 8; k++) acc[r][k] = fmaxf(acc[r][k], acc[r][k - 1]);
    // exclusive lane-carry scans, 4 chains interleaved
    float e0 = __shfl_up_sync(FULLM, acc[0][7], 1);
    float e1 = __shfl_up_sync(FULLM, acc[1][7], 1);
    float e2 = __shfl_up_sync(FULLM, acc[2][7], 1);
    float e3 = __shfl_up_sync(FULLM, acc[3][7], 1);
    if (lane == 0) { e0 = NEGV; e1 = NEGV; e2 = NEGV; e3 = NEGV; }
#pragma unroll
    for (int d = 1; d < 32; d <<= 1) {
        float o0 = __shfl_up_sync(FULLM, e0, d);
        float o1 = __shfl_up_sync(FULLM, e1, d);
        float o2 = __shfl_up_sync(FULLM, e2, d);
        float o3 = __shfl_up_sync(FULLM, e3, d);
        e0 = fmaxf(e0, o0);
        e1 = fmaxf(e1, o1);
        e2 = fmaxf(e2, o2);
        e3 = fmaxf(e3, o3);
    }
    // vertical cummax + merge old M
#pragma unroll
    for (int k = 0; k < 8; k++) {
        rr[0][k] = fmaxf(M[k],     fmaxf(acc[0][k], e0));
        rr[1][k] = fmaxf(rr[0][k], fmaxf(acc[1][k], e1));
        rr[2][k] = fmaxf(rr[1][k], fmaxf(acc[2][k], e2));
        rr[3][k] = fmaxf(rr[2][k], fmaxf(acc[3][k], e3));
    }
}

template <int P2, int P3, int P4>
__device__ __forceinline__ float tree_warp(const float* __restrict__ rowp,
                                           int lane, bool act,
                                           float2 A0, float2 A1, float2 A2,
                                           float2 A3, float2 A4) {
    float M1[8], M2[8], M3[8], M4[8];
#pragma unroll
    for (int k = 0; k < 8; k++) { M1[k] = NEGV; M2[k] = NEGV; M3[k] = NEGV; M4[k] = NEGV; }
    float runmax = NEGV;

#pragma unroll 1
    for (int blk = 0; blk < H_ / 4; blk++) {
        float xv[4][8];
#pragma unroll
        for (int r = 0; r < 4; r++) {
            if (act) {
                float4 u0 = *reinterpret_cast<const float4*>(rowp + r * W_);
                float4 u1 = *reinterpret_cast<const float4*>(rowp + r * W_ + 4);
                xv[r][0] = u0.x; xv[r][1] = u0.y; xv[r][2] = u0.z; xv[r][3] = u0.w;
                xv[r][4] = u1.x; xv[r][5] = u1.y; xv[r][6] = u1.z; xv[r][7] = u1.w;
            } else {
#pragma unroll
                for (int k = 0; k < 8; k++) xv[r][k] = NEGV;
            }
        }

        float r4[4][8], r3[4][8], r2[4][8], r1[4][8];
        {   // node 4 (leaf)
            float acc[4][8];
            build_acc(acc, xv, A4);
            scan_block(acc, M4, r4, lane);
        }
        {   // node 3
            float acc[4][8];
            build_acc(acc, xv, A3);
            if (P4 == 3) add_shift(acc, M4, r4, lane);
            scan_block(acc, M3, r3, lane);
        }
        {   // node 2
            float acc[4][8];
            build_acc(acc, xv, A2);
            if (P3 == 2) add_shift(acc, M3, r3, lane);
            if (P4 == 2) add_shift(acc, M4, r4, lane);
            scan_block(acc, M2, r2, lane);
        }
        {   // node 1
            float acc[4][8];
            build_acc(acc, xv, A1);
            if (P2 == 1) add_shift(acc, M2, r2, lane);
            if (P3 == 1) add_shift(acc, M3, r3, lane);
            if (P4 == 1) add_shift(acc, M4, r4, lane);
            scan_block(acc, M1, r1, lane);
        }
        {   // root (node 0): no scan, just plane max
            float acc[4][8];
            build_acc(acc, xv, A0);
            add_shift(acc, M1, r1, lane);  // node 1 always child of root
            if (P2 == 0) add_shift(acc, M2, r2, lane);
            if (P3 == 0) add_shift(acc, M3, r3, lane);
            if (P4 == 0) add_shift(acc, M4, r4, lane);
#pragma unroll
            for (int r = 0; r < 4; r++)
#pragma unroll
                for (int k = 0; k < 8; k++) runmax = fmaxf(runmax, acc[r][k]);
        }
        // commit running states
#pragma unroll
        for (int k = 0; k < 8; k++) {
            M4[k] = r4[3][k]; M3[k] = r3[3][k];
            M2[k] = r2[3][k]; M1[k] = r1[3][k];
        }
        rowp += 4 * W_;
    }

#pragma unroll
    for (int d = 16; d; d >>= 1)
        runmax = fmaxf(runmax, __shfl_xor_sync(FULLM, runmax, d));
    return runmax;
}

__global__ void __launch_bounds__(32)
forest_kernel(const float* __restrict__ alphas, float* __restrict__ out, Forest f) {
    int blk = blockIdx.x;
    int t = blk >> 7;           // high bits: same-tree blocks contiguous (I$ locality)
    int b = (blk >> 4) & 7;
    int c = blk & 15;
    int lane = threadIdx.x;
    const bool act = lane < 28;

    const float* plane = g_xv + (size_t)(b * C_ + c) * (H_ * W_);
    const float* rowp = plane + lane * 8;

    float2 A[N_];
#pragma unroll
    for (int i = 0; i < N_; i++) {
        float av = alphas[(t * N_ + i) * C_ + c];
        A[i] = make_float2(av, av);
    }

    const int p2 = f.par[t][2], p3 = f.par[t][3], p4 = f.par[t][4];
    int code = p2 * 12 + p3 * 4 + p4;

    float res = NEGV;
    switch (code) {
#define CASE_T(P2V, P3V, P4V)                                                  \
    case (P2V * 12 + P3V * 4 + P4V):                                           \
        res = tree_warp<P2V, P3V, P4V>(rowp, lane, act, A[0], A[1], A[2],      \
                                       A[3], A[4]);                            \
        break;
        CASE_T(0,0,0) CASE_T(0,0,1) CASE_T(0,0,2) CASE_T(0,0,3)
        CASE_T(0,1,0) CASE_T(0,1,1) CASE_T(0,1,2) CASE_T(0,1,3)
        CASE_T(0,2,0) CASE_T(0,2,1) CASE_T(0,2,2) CASE_T(0,2,3)
        CASE_T(1,0,0) CASE_T(1,0,1) CASE_T(1,0,2) CASE_T(1,0,3)
        CASE_T(1,1,0) CASE_T(1,1,1) CASE_T(1,1,2) CASE_T(1,1,3)
        CASE_T(1,2,0) CASE_T(1,2,1) CASE_T(1,2,2) CASE_T(1,2,3)
#undef CASE_T
        default: break;
    }

    if (lane == 0)
        out[(b * T_ + t) * C_ + c] = expm1f(res);
}

// ============================================================================
// Host: exact replication of np.random.default_rng(0) draws used by
// make_forest(): SeedSequence(0) -> PCG64 (XSL-RR 128/64) -> Generator
// .integers(0, i) (Lemire, buffered 32-bit path) for i = 1..4 per tree.
// ============================================================================

static inline uint32_t hashmix_(uint32_t v, uint32_t* hc) {
    v ^= *hc;
    *hc *= 0x931e8875u;   // MULT_A
    v *= *hc;
    v ^= v >> 16;
    return v;
}
static inline uint32_t mix_(uint32_t x, uint32_t y) {
    uint32_t r = x * 0xca01f9ddu - y * 0x4973f715u;  // MIX_MULT_L/R
    r ^= r >> 16;
    return r;
}

static void compute_forest(Forest* f) {
    uint32_t pool[4];
    uint32_t hc = 0x43b0d7e5u;  // INIT_A
    for (int i = 0; i < 4; i++) pool[i] = hashmix_(0u, &hc);
    for (int s = 0; s < 4; s++)
        for (int d = 0; d < 4; d++)
            if (s != d) pool[d] = mix_(pool[d], hashmix_(pool[s], &hc));

    uint32_t hb = 0x8b51f9ddu;  // INIT_B
    uint32_t w32[8];
    for (int i = 0; i < 8; i++) {
        uint32_t dv = pool[i & 3];
        dv ^= hb;
        hb *= 0x58f38dedu;  // MULT_B
        dv *= hb;
        dv ^= dv >> 16;
        w32[i] = dv;
    }
    uint64_t val[4];
    for (int i = 0; i < 4; i++)
        val[i] = (uint64_t)w32[2 * i] | ((uint64_t)w32[2 * i + 1] << 32);

    typedef unsigned __int128 u128;
    const u128 MULT = ((u128)2549297995355413924ULL << 64) | 4865540595714422341ULL;
    u128 initstate = ((u128)val[0] << 64) | (u128)val[1];
    u128 inc = (((((u128)val[2] << 64) | (u128)val[3])) << 1) | 1;
    u128 state = inc;
    state += initstate;
    state = state * MULT + inc;

    int has32 = 0;
    uint32_t cached = 0;

    for (int t = 0; t < T_; t++) {
        f->par[t][0] = -1;
        f->par[t][1] = 0;  // integers(0,1): rng==0, no draw consumed
        for (int i = 2; i < N_; i++) {
            uint32_t rng = (uint32_t)i - 1u;
            uint32_t rng_excl = rng + 1u;
            uint64_t m;
            uint32_t leftover;
            for (;;) {
                uint32_t r32;
                if (has32) {
                    has32 = 0;
                    r32 = cached;
                } else {
                    state = state * MULT + inc;
                    uint64_t hi = (uint64_t)(state >> 64);
                    uint64_t lo = (uint64_t)state;
                    unsigned rot = (unsigned)(uint64_t)(state >> 122);
                    uint64_t x = hi ^ lo;
                    uint64_t o = (x >> rot) | (x << ((64u - rot) & 63u));
                    has32 = 1;
                    cached = (uint32_t)(o >> 32);
                    r32 = (uint32_t)o;
                }
                m = (uint64_t)r32 * (uint64_t)rng_excl;
                leftover = (uint32_t)m;
                if (leftover >= rng_excl) break;
                uint32_t thr = (0xFFFFFFFFu - rng) % rng_excl;
                if (leftover >= thr) break;
            }
            f->par[t][i] = (int)(uint32_t)(m >> 32);
        }
    }
}

extern "C" void kernel_launch(void* const* d_in, const int* in_sizes, int n_in,
                              void* d_out, int out_size) {
    const float* x = (const float*)d_in[0];
    const float* alphas = (const float*)d_in[1];
    float* out = (float*)d_out;

    Forest f;
    compute_forest(&f);

    xv_kernel<<<NTOT / 4 / 256, 256>>>(x);
    forest_kernel<<<B_ * C_ * T_, 32>>>(alphas, out, f);
}

// round 7
// speedup vs baseline: 2.8453x; 2.8453x over previous
#include <cuda_runtime.h>
#include <cstdint>

#define B_ 8
#define C_ 16
#define H_ 224
#define W_ 224
#define T_ 8
#define N_ 5
#define NEGV (-1e30f)
#define NTOT (B_*C_*H_*W_)
#define FULLW 0xffffffffu

// Scratch: xv = log1p(relu(x)); padded one row for unconditional prefetch.
__device__ float g_xv[NTOT + W_];

__global__ void xv_kernel(const float* __restrict__ x) {
    int n4 = NTOT / 4;
    for (int i = blockIdx.x * blockDim.x + threadIdx.x; i < n4;
         i += gridDim.x * blockDim.x) {
        float4 v = reinterpret_cast<const float4*>(x)[i];
        v.x = log1pf(fmaxf(v.x, 0.f));
        v.y = log1pf(fmaxf(v.y, 0.f));
        v.z = log1pf(fmaxf(v.z, 0.f));
        v.w = log1pf(fmaxf(v.w, 0.f));
        reinterpret_cast<float4*>(g_xv)[i] = v;
    }
}

struct Forest { int par[T_][N_]; };

// ============================================================================
// Compile-time plan: alphas factor out of prefix-max (P(f+c)=P(f)+c), so each
// node contributes a pure SHAPE function T_s = P(xv + sum of child T's).
// Nodes with equal subtree shapes share one scan slot. Root value =
// xv + sum over root children of (shifted slot state) with multiplicity.
// ============================================================================
struct Plan {
    int ns;              // number of scan slots
    int childCnt[4][4];  // childCnt[slot][childSlot] multiplicity
    int rootCnt[4];      // multiplicity of slot as a root child
};

__host__ __device__ constexpr Plan makePlan(int P2, int P3, int P4) {
    Plan pl{};
    int par[5] = {-1, 0, P2, P3, P4};
    // shape registry: entry = sorted (desc) child-shape-id triple
    int regA[8] = {}, regB[8] = {}, regC[8] = {};
    int nreg = 1;  // id 0 = leaf: (-1,-1,-1)
    regA[0] = -1; regB[0] = -1; regC[0] = -1;
    int shape[5] = {0, 0, 0, 0, 0};
    for (int i = 4; i >= 1; i--) {
        int k[3] = {-1, -1, -1};
        int nk = 0;
        for (int m = i + 1; m <= 4; m++)
            if (par[m] == i) k[nk++] = shape[m];
        for (int a = 0; a < 3; a++)
            for (int b = a + 1; b < 3; b++)
                if (k[b] > k[a]) { int tm = k[a]; k[a] = k[b]; k[b] = tm; }
        int id = -1;
        for (int r = 0; r < nreg; r++)
            if (regA[r] == k[0] && regB[r] == k[1] && regC[r] == k[2]) id = r;
        if (id < 0) {
            regA[nreg] = k[0]; regB[nreg] = k[1]; regC[nreg] = k[2];
            id = nreg++;
        }
        shape[i] = id;
    }
    // assign slots (processing order nodes 4..1, first occurrence of a shape)
    int slotOfShape[8] = {-1, -1, -1, -1, -1, -1, -1, -1};
    int slotOfNode[5] = {0, 0, 0, 0, 0};
    pl.ns = 0;
    for (int i = 4; i >= 1; i--) {
        int s = shape[i];
        if (slotOfShape[s] < 0) {
            int sl = pl.ns;
            pl.ns = pl.ns + 1;
            slotOfShape[s] = sl;
            for (int m = i + 1; m <= 4; m++)
                if (par[m] == i) pl.childCnt[sl][slotOfNode[m]]++;
        }
        slotOfNode[i] = slotOfShape[s];
    }
    for (int m = 1; m <= 4; m++)
        if (par[m] == 0) pl.rootCnt[slotOfNode[m]]++;
    return pl;
}

// dst[k] += C * shifted(Mc)[k], shifted = (Bnd at k==0, Mc[k-1] else)
template <int CNT>
__device__ __forceinline__ void add_shift(float dst[8], const float Mc[8],
                                          float bndc) {
    if (CNT == 1) {
        dst[0] += bndc;
#pragma unroll
        for (int k = 1; k < 8; k++) dst[k] += Mc[k - 1];
    } else {
        dst[0] = fmaf((float)CNT, bndc, dst[0]);
#pragma unroll
        for (int k = 1; k < 8; k++) dst[k] = fmaf((float)CNT, Mc[k - 1], dst[k]);
    }
}

template <int P2, int P3, int P4>
__device__ __forceinline__ float tree_warp(const float* __restrict__ rowp,
                                           int lane, bool act) {
    constexpr Plan pl = makePlan(P2, P3, P4);
    constexpr int NS = pl.ns;

    // M[s]: inclusive 2D cummax of shape slot s (28 lanes x 8 cols).
    // Bnd[s]: M[s][7] of the lane to the left (boundary), via recurrence.
    float M[NS][8];
    float Bnd[NS];
#pragma unroll
    for (int s = 0; s < NS; s++) {
        Bnd[s] = NEGV;
#pragma unroll
        for (int k = 0; k < 8; k++) M[s][k] = NEGV;
    }
    float runmax = NEGV;

    // double-buffered row loads
    float4 c0, c1;
    if (act) {
        c0 = *reinterpret_cast<const float4*>(rowp);
        c1 = *reinterpret_cast<const float4*>(rowp + 4);
    } else {
        c0 = make_float4(NEGV, NEGV, NEGV, NEGV);
        c1 = c0;
    }

#pragma unroll 1
    for (int h = 0; h < H_; h++) {
        const float* nrp = rowp + W_;
        float4 n0, n1;
        if (act) {
            n0 = *reinterpret_cast<const float4*>(nrp);
            n1 = *reinterpret_cast<const float4*>(nrp + 4);
        } else { n0 = make_float4(NEGV, NEGV, NEGV, NEGV); n1 = n0; }

        float xv[8] = {c0.x, c0.y, c0.z, c0.w, c1.x, c1.y, c1.z, c1.w};

        // ---- root value + plane max (uses OLD slot states, shifted) ----
        {
            float r[8];
#pragma unroll
            for (int k = 0; k < 8; k++) r[k] = xv[k];
#pragma unroll
            for (int s = 0; s < NS; s++) {
                if (pl.rootCnt[s] == 1) add_shift<1>(r, M[s], Bnd[s]);
                else if (pl.rootCnt[s] == 2) add_shift<2>(r, M[s], Bnd[s]);
                else if (pl.rootCnt[s] == 3) add_shift<3>(r, M[s], Bnd[s]);
                else if (pl.rootCnt[s] == 4) add_shift<4>(r, M[s], Bnd[s]);
            }
#pragma unroll
            for (int k = 0; k < 8; k++) runmax = fmaxf(runmax, r[k]);
        }

        // ---- build accs for all slots (from OLD child states, shifted) ----
        float acc[NS][8];
#pragma unroll
        for (int s = 0; s < NS; s++) {
#pragma unroll
            for (int k = 0; k < 8; k++) acc[s][k] = xv[k];
#pragma unroll
            for (int cs = 0; cs < NS; cs++) {
                if (pl.childCnt[s][cs] == 1) add_shift<1>(acc[s], M[cs], Bnd[cs]);
                else if (pl.childCnt[s][cs] == 2) add_shift<2>(acc[s], M[cs], Bnd[cs]);
                else if (pl.childCnt[s][cs] == 3) add_shift<3>(acc[s], M[cs], Bnd[cs]);
            }
        }

        // ---- fused scans: chunk prefix, then interleaved lane scans ----
#pragma unroll
        for (int s = 0; s < NS; s++)
#pragma unroll
            for (int k = 1; k < 8; k++)
                acc[s][k] = fmaxf(acc[s][k], acc[s][k - 1]);

        float e[NS];
#pragma unroll
        for (int s = 0; s < NS; s++) {
            e[s] = __shfl_up_sync(FULLW, acc[s][7], 1);
            if (lane == 0) e[s] = NEGV;
        }
#pragma unroll
        for (int d = 1; d < 32; d <<= 1) {
            float o[NS];
#pragma unroll
            for (int s = 0; s < NS; s++) o[s] = __shfl_up_sync(FULLW, e[s], d);
#pragma unroll
            for (int s = 0; s < NS; s++) e[s] = fmaxf(e[s], o[s]);
        }

        // ---- merge + boundary recurrence (no shfl needed) ----
#pragma unroll
        for (int s = 0; s < NS; s++) {
#pragma unroll
            for (int k = 0; k < 8; k++)
                M[s][k] = fmaxf(M[s][k], fmaxf(acc[s][k], e[s]));
            Bnd[s] = fmaxf(Bnd[s], e[s]);
        }

        c0 = n0; c1 = n1;
        rowp = nrp;
    }

#pragma unroll
    for (int d = 16; d; d >>= 1)
        runmax = fmaxf(runmax, __shfl_xor_sync(FULLW, runmax, d));
    return runmax;
}

__global__ void __launch_bounds__(32)
forest_kernel(const float* __restrict__ alphas, float* __restrict__ out, Forest f) {
    int blk = blockIdx.x;
    int t = blk & 7;            // low bits: trees interleaved across SMs
    int c = (blk >> 3) & 15;
    int b = blk >> 7;
    int lane = threadIdx.x;
    const bool act = lane < 28;

    const float* plane = g_xv + (size_t)(b * C_ + c) * (H_ * W_);
    const float* rowp = plane + lane * 8;

    const int p2 = f.par[t][2], p3 = f.par[t][3], p4 = f.par[t][4];
    int code = p2 * 12 + p3 * 4 + p4;

    float res = NEGV;
    switch (code) {
#define CASE_T(P2V, P3V, P4V)                                                  \
    case (P2V * 12 + P3V * 4 + P4V):                                           \
        res = tree_warp<P2V, P3V, P4V>(rowp, lane, act);                       \
        break;
        CASE_T(0,0,0) CASE_T(0,0,1) CASE_T(0,0,2) CASE_T(0,0,3)
        CASE_T(0,1,0) CASE_T(0,1,1) CASE_T(0,1,2) CASE_T(0,1,3)
        CASE_T(0,2,0) CASE_T(0,2,1) CASE_T(0,2,2) CASE_T(0,2,3)
        CASE_T(1,0,0) CASE_T(1,0,1) CASE_T(1,0,2) CASE_T(1,0,3)
        CASE_T(1,1,0) CASE_T(1,1,1) CASE_T(1,1,2) CASE_T(1,1,3)
        CASE_T(1,2,0) CASE_T(1,2,1) CASE_T(1,2,2) CASE_T(1,2,3)
#undef CASE_T
        default: break;
    }

    if (lane == 0) {
        // K = sum of all 5 alphas for this (t, channel)
        float K = 0.f;
#pragma unroll
        for (int i = 0; i < N_; i++) K += alphas[(t * N_ + i) * C_ + c];
        out[(b * T_ + t) * C_ + c] = expm1f(res + K);
    }
}

// ============================================================================
// Host: exact replication of np.random.default_rng(0) draws used by
// make_forest(): SeedSequence(0) -> PCG64 (XSL-RR 128/64) -> Generator
// .integers(0, i) (Lemire, buffered 32-bit path) for i = 1..4 per tree.
// ============================================================================

static inline uint32_t hashmix_(uint32_t v, uint32_t* hc) {
    v ^= *hc;
    *hc *= 0x931e8875u;   // MULT_A
    v *= *hc;
    v ^= v >> 16;
    return v;
}
static inline uint32_t mix_(uint32_t x, uint32_t y) {
    uint32_t r = x * 0xca01f9ddu - y * 0x4973f715u;  // MIX_MULT_L/R
    r ^= r >> 16;
    return r;
}

static void compute_forest(Forest* f) {
    uint32_t pool[4];
    uint32_t hc = 0x43b0d7e5u;  // INIT_A
    for (int i = 0; i < 4; i++) pool[i] = hashmix_(0u, &hc);
    for (int s = 0; s < 4; s++)
        for (int d = 0; d < 4; d++)
            if (s != d) pool[d] = mix_(pool[d], hashmix_(pool[s], &hc));

    uint32_t hb = 0x8b51f9ddu;  // INIT_B
    uint32_t w32[8];
    for (int i = 0; i < 8; i++) {
        uint32_t dv = pool[i & 3];
        dv ^= hb;
        hb *= 0x58f38dedu;  // MULT_B
        dv *= hb;
        dv ^= dv >> 16;
        w32[i] = dv;
    }
    uint64_t val[4];
    for (int i = 0; i < 4; i++)
        val[i] = (uint64_t)w32[2 * i] | ((uint64_t)w32[2 * i + 1] << 32);

    typedef unsigned __int128 u128;
    const u128 MULT = ((u128)2549297995355413924ULL << 64) | 4865540595714422341ULL;
    u128 initstate = ((u128)val[0] << 64) | (u128)val[1];
    u128 inc = (((((u128)val[2] << 64) | (u128)val[3])) << 1) | 1;
    u128 state = inc;
    state += initstate;
    state = state * MULT + inc;

    int has32 = 0;
    uint32_t cached = 0;

    for (int t = 0; t < T_; t++) {
        f->par[t][0] = -1;
        f->par[t][1] = 0;  // integers(0,1): rng==0, no draw consumed
        for (int i = 2; i < N_; i++) {
            uint32_t rng = (uint32_t)i - 1u;
            uint32_t rng_excl = rng + 1u;
            uint64_t m;
            uint32_t leftover;
            for (;;) {
                uint32_t r32;
                if (has32) {
                    has32 = 0;
                    r32 = cached;
                } else {
                    state = state * MULT + inc;
                    uint64_t hi = (uint64_t)(state >> 64);
                    uint64_t lo = (uint64_t)state;
                    unsigned rot = (unsigned)(uint64_t)(state >> 122);
                    uint64_t x = hi ^ lo;
                    uint64_t o = (x >> rot) | (x << ((64u - rot) & 63u));
                    has32 = 1;
                    cached = (uint32_t)(o >> 32);
                    r32 = (uint32_t)o;
                }
                m = (uint64_t)r32 * (uint64_t)rng_excl;
                leftover = (uint32_t)m;
                if (leftover >= rng_excl) break;
                uint32_t thr = (0xFFFFFFFFu - rng) % rng_excl;
                if (leftover >= thr) break;
            }
            f->par[t][i] = (int)(uint32_t)(m >> 32);
        }
    }
}

extern "C" void kernel_launch(void* const* d_in, const int* in_sizes, int n_in,
                              void* d_out, int out_size) {
    const float* x = (const float*)d_in[0];
    const float* alphas = (const float*)d_in[1];
    float* out = (float*)d_out;

    Forest f;
    compute_forest(&f);

    xv_kernel<<<NTOT / 4 / 256, 256>>>(x);
    forest_kernel<<<B_ * C_ * T_, 32>>>(alphas, out, f);
}

// round 8
// speedup vs baseline: 3.1076x; 1.0922x over previous
#include <cuda_runtime.h>
#include <cstdint>

#define B_ 8
#define C_ 16
#define H_ 224
#define W_ 224
#define T_ 8
#define N_ 5
#define NEGV (-1e30f)
#define NTOT (B_*C_*H_*W_)
#define FULLW 0xffffffffu

// Scratch: xv = log1p(relu(x)); padded one row for unconditional prefetch.
__device__ float g_xv[NTOT + W_];

__global__ void xv_kernel(const float* __restrict__ x) {
    int n4 = NTOT / 4;
    for (int i = blockIdx.x * blockDim.x + threadIdx.x; i < n4;
         i += gridDim.x * blockDim.x) {
        float4 v = reinterpret_cast<const float4*>(x)[i];
        v.x = log1pf(fmaxf(v.x, 0.f));
        v.y = log1pf(fmaxf(v.y, 0.f));
        v.z = log1pf(fmaxf(v.z, 0.f));
        v.w = log1pf(fmaxf(v.w, 0.f));
        reinterpret_cast<float4*>(g_xv)[i] = v;
    }
}

struct Forest { int par[T_][N_]; };

// ============================================================================
// Compile-time plan: alphas factor out of prefix-max (P(f+c)=P(f)+c), so each
// node contributes a pure SHAPE function T_s = P(xv + sum of child T's).
// Nodes with equal subtree shapes share one scan slot.
// ============================================================================
struct Plan {
    int ns;
    int childCnt[4][4];
    int rootCnt[4];
};

__host__ __device__ constexpr Plan makePlan(int P2, int P3, int P4) {
    Plan pl{};
    int par[5] = {-1, 0, P2, P3, P4};
    int regA[8] = {}, regB[8] = {}, regC[8] = {};
    int nreg = 1;
    regA[0] = -1; regB[0] = -1; regC[0] = -1;
    int shape[5] = {0, 0, 0, 0, 0};
    for (int i = 4; i >= 1; i--) {
        int k[3] = {-1, -1, -1};
        int nk = 0;
        for (int m = i + 1; m <= 4; m++)
            if (par[m] == i) k[nk++] = shape[m];
        for (int a = 0; a < 3; a++)
            for (int b = a + 1; b < 3; b++)
                if (k[b] > k[a]) { int tm = k[a]; k[a] = k[b]; k[b] = tm; }
        int id = -1;
        for (int r = 0; r < nreg; r++)
            if (regA[r] == k[0] && regB[r] == k[1] && regC[r] == k[2]) id = r;
        if (id < 0) {
            regA[nreg] = k[0]; regB[nreg] = k[1]; regC[nreg] = k[2];
            id = nreg++;
        }
        shape[i] = id;
    }
    int slotOfShape[8] = {-1, -1, -1, -1, -1, -1, -1, -1};
    int slotOfNode[5] = {0, 0, 0, 0, 0};
    pl.ns = 0;
    for (int i = 4; i >= 1; i--) {
        int s = shape[i];
        if (slotOfShape[s] < 0) {
            int sl = pl.ns;
            pl.ns = pl.ns + 1;
            slotOfShape[s] = sl;
            for (int m = i + 1; m <= 4; m++)
                if (par[m] == i) pl.childCnt[sl][slotOfNode[m]]++;
        }
        slotOfNode[i] = slotOfShape[s];
    }
    for (int m = 1; m <= 4; m++)
        if (par[m] == 0) pl.rootCnt[slotOfNode[m]]++;
    return pl;
}

// dst[k] += C * shifted(Mc)[k], shifted = (Bnd at k==0, Mc[k-1] else)
template <int CNT>
__device__ __forceinline__ void add_shift(float dst[8], const float Mc[8],
                                          float bndc) {
    if (CNT == 1) {
        dst[0] += bndc;
#pragma unroll
        for (int k = 1; k < 8; k++) dst[k] += Mc[k - 1];
    } else {
        dst[0] = fmaf((float)CNT, bndc, dst[0]);
#pragma unroll
        for (int k = 1; k < 8; k++) dst[k] = fmaf((float)CNT, Mc[k - 1], dst[k]);
    }
}

template <int P2, int P3, int P4>
__device__ __forceinline__ float tree_warp(const float* __restrict__ rowp,
                                           int lane, bool act,
                                           float (*s_gtot)[16],
                                           float (*s_gpref)[16]) {
    constexpr Plan pl = makePlan(P2, P3, P4);
    constexpr int NS = pl.ns;

    float M[NS][8];
    float Bnd[NS];
#pragma unroll
    for (int s = 0; s < NS; s++) {
        Bnd[s] = NEGV;
#pragma unroll
        for (int k = 0; k < 8; k++) M[s][k] = NEGV;
    }
    float runmax = NEGV;
    const int pair = lane >> 1;
    const bool isOdd = (lane & 1) != 0;

    float4 c0, c1;
    if (act) {
        c0 = *reinterpret_cast<const float4*>(rowp);
        c1 = *reinterpret_cast<const float4*>(rowp + 4);
    } else {
        c0 = make_float4(NEGV, NEGV, NEGV, NEGV);
        c1 = c0;
    }

#pragma unroll 1
    for (int h = 0; h < H_; h++) {
        const float* nrp = rowp + W_;
        float4 n0, n1;
        if (act) {
            n0 = *reinterpret_cast<const float4*>(nrp);
            n1 = *reinterpret_cast<const float4*>(nrp + 4);
        } else { n0 = make_float4(NEGV, NEGV, NEGV, NEGV); n1 = n0; }

        float xv[8] = {c0.x, c0.y, c0.z, c0.w, c1.x, c1.y, c1.z, c1.w};

        // ---- root value + plane max (OLD slot states, shifted) ----
        {
            float r[8];
#pragma unroll
            for (int k = 0; k < 8; k++) r[k] = xv[k];
#pragma unroll
            for (int s = 0; s < NS; s++) {
                if (pl.rootCnt[s] == 1) add_shift<1>(r, M[s], Bnd[s]);
                else if (pl.rootCnt[s] == 2) add_shift<2>(r, M[s], Bnd[s]);
                else if (pl.rootCnt[s] == 3) add_shift<3>(r, M[s], Bnd[s]);
                else if (pl.rootCnt[s] == 4) add_shift<4>(r, M[s], Bnd[s]);
            }
#pragma unroll
            for (int k = 0; k < 8; k++) runmax = fmaxf(runmax, r[k]);
        }

        // ---- build accs for all slots (OLD child states, shifted) ----
        float acc[NS][8];
#pragma unroll
        for (int s = 0; s < NS; s++) {
#pragma unroll
            for (int k = 0; k < 8; k++) acc[s][k] = xv[k];
#pragma unroll
            for (int cs = 0; cs < NS; cs++) {
                if (pl.childCnt[s][cs] == 1) add_shift<1>(acc[s], M[cs], Bnd[cs]);
                else if (pl.childCnt[s][cs] == 2) add_shift<2>(acc[s], M[cs], Bnd[cs]);
                else if (pl.childCnt[s][cs] == 3) add_shift<3>(acc[s], M[cs], Bnd[cs]);
            }
        }

        // ---- chunk prefix per slot (interleaved fmax chains) ----
#pragma unroll
        for (int s = 0; s < NS; s++)
#pragma unroll
            for (int k = 1; k < 8; k++)
                acc[s][k] = fmaxf(acc[s][k], acc[s][k - 1]);

        // ---- hierarchical exclusive scan over 28 chunk totals:
        //      pairs (1 SHFL/slot) + 14-group smem stage ----
        float ptot[NS];
#pragma unroll
        for (int s = 0; s < NS; s++)
            ptot[s] = __shfl_xor_sync(FULLW, acc[s][7], 1);
        if (!isOdd) {
#pragma unroll
            for (int s = 0; s < NS; s++)
                s_gtot[s][pair] = fmaxf(acc[s][7], ptot[s]);
        }
        __syncwarp();
        if (lane < NS) {
            const float4* g4 = reinterpret_cast<const float4*>(s_gtot[lane]);
            float4 G0 = g4[0], G1 = g4[1], G2 = g4[2], G3 = g4[3];
            float p1  = G0.x;
            float p2  = fmaxf(p1,  G0.y);
            float p3  = fmaxf(p2,  G0.z);
            float p4  = fmaxf(p3,  G0.w);
            float p5  = fmaxf(p4,  G1.x);
            float p6  = fmaxf(p5,  G1.y);
            float p7  = fmaxf(p6,  G1.z);
            float p8  = fmaxf(p7,  G1.w);
            float p9  = fmaxf(p8,  G2.x);
            float p10 = fmaxf(p9,  G2.y);
            float p11 = fmaxf(p10, G2.z);
            float p12 = fmaxf(p11, G2.w);
            float p13 = fmaxf(p12, G3.x);
            float p14 = fmaxf(p13, G3.y);
            float p15 = fmaxf(p14, G3.z);
            float4* o4 = reinterpret_cast<float4*>(s_gpref[lane]);
            o4[0] = make_float4(NEGV, p1, p2, p3);
            o4[1] = make_float4(p4, p5, p6, p7);
            o4[2] = make_float4(p8, p9, p10, p11);
            o4[3] = make_float4(p12, p13, p14, p15);
        }
        __syncwarp();

        // ---- merge + boundary recurrence ----
#pragma unroll
        for (int s = 0; s < NS; s++) {
            float within = isOdd ? ptot[s] : NEGV;
            float e = fmaxf(s_gpref[s][pair], within);
#pragma unroll
            for (int k = 0; k < 8; k++)
                M[s][k] = fmaxf(M[s][k], fmaxf(acc[s][k], e));
            Bnd[s] = fmaxf(Bnd[s], e);
        }

        c0 = n0; c1 = n1;
        rowp = nrp;
    }

#pragma unroll
    for (int d = 16; d; d >>= 1)
        runmax = fmaxf(runmax, __shfl_xor_sync(FULLW, runmax, d));
    return runmax;
}

__global__ void __launch_bounds__(32)
forest_kernel(const float* __restrict__ alphas, float* __restrict__ out, Forest f) {
    __shared__ __align__(16) float s_gtot[4][16];
    __shared__ __align__(16) float s_gpref[4][16];

    int blk = blockIdx.x;
    int t = blk & 7;            // low bits: trees interleaved across SMs
    int c = (blk >> 3) & 15;
    int b = blk >> 7;
    int lane = threadIdx.x;
    const bool act = lane < 28;

    const float* plane = g_xv + (size_t)(b * C_ + c) * (H_ * W_);
    const float* rowp = plane + lane * 8;

    const int p2 = f.par[t][2], p3 = f.par[t][3], p4 = f.par[t][4];
    int code = p2 * 12 + p3 * 4 + p4;

    float res = NEGV;
    switch (code) {
#define CASE_T(P2V, P3V, P4V)                                                  \
    case (P2V * 12 + P3V * 4 + P4V):                                           \
        res = tree_warp<P2V, P3V, P4V>(rowp, lane, act, s_gtot, s_gpref);      \
        break;
        CASE_T(0,0,0) CASE_T(0,0,1) CASE_T(0,0,2) CASE_T(0,0,3)
        CASE_T(0,1,0) CASE_T(0,1,1) CASE_T(0,1,2) CASE_T(0,1,3)
        CASE_T(0,2,0) CASE_T(0,2,1) CASE_T(0,2,2) CASE_T(0,2,3)
        CASE_T(1,0,0) CASE_T(1,0,1) CASE_T(1,0,2) CASE_T(1,0,3)
        CASE_T(1,1,0) CASE_T(1,1,1) CASE_T(1,1,2) CASE_T(1,1,3)
        CASE_T(1,2,0) CASE_T(1,2,1) CASE_T(1,2,2) CASE_T(1,2,3)
#undef CASE_T
        default: break;
    }

    if (lane == 0) {
        float K = 0.f;
#pragma unroll
        for (int i = 0; i < N_; i++) K += alphas[(t * N_ + i) * C_ + c];
        out[(b * T_ + t) * C_ + c] = expm1f(res + K);
    }
}

// ============================================================================
// Host: exact replication of np.random.default_rng(0) draws used by
// make_forest(): SeedSequence(0) -> PCG64 (XSL-RR 128/64) -> Generator
// .integers(0, i) (Lemire, buffered 32-bit path) for i = 1..4 per tree.
// ============================================================================

static inline uint32_t hashmix_(uint32_t v, uint32_t* hc) {
    v ^= *hc;
    *hc *= 0x931e8875u;   // MULT_A
    v *= *hc;
    v ^= v >> 16;
    return v;
}
static inline uint32_t mix_(uint32_t x, uint32_t y) {
    uint32_t r = x * 0xca01f9ddu - y * 0x4973f715u;  // MIX_MULT_L/R
    r ^= r >> 16;
    return r;
}

static void compute_forest(Forest* f) {
    uint32_t pool[4];
    uint32_t hc = 0x43b0d7e5u;  // INIT_A
    for (int i = 0; i < 4; i++) pool[i] = hashmix_(0u, &hc);
    for (int s = 0; s < 4; s++)
        for (int d = 0; d < 4; d++)
            if (s != d) pool[d] = mix_(pool[d], hashmix_(pool[s], &hc));

    uint32_t hb = 0x8b51f9ddu;  // INIT_B
    uint32_t w32[8];
    for (int i = 0; i < 8; i++) {
        uint32_t dv = pool[i & 3];
        dv ^= hb;
        hb *= 0x58f38dedu;  // MULT_B
        dv *= hb;
        dv ^= dv >> 16;
        w32[i] = dv;
    }
    uint64_t val[4];
    for (int i = 0; i < 4; i++)
        val[i] = (uint64_t)w32[2 * i] | ((uint64_t)w32[2 * i + 1] << 32);

    typedef unsigned __int128 u128;
    const u128 MULT = ((u128)2549297995355413924ULL << 64) | 4865540595714422341ULL;
    u128 initstate = ((u128)val[0] << 64) | (u128)val[1];
    u128 inc = (((((u128)val[2] << 64) | (u128)val[3])) << 1) | 1;
    u128 state = inc;
    state += initstate;
    state = state * MULT + inc;

    int has32 = 0;
    uint32_t cached = 0;

    for (int t = 0; t < T_; t++) {
        f->par[t][0] = -1;
        f->par[t][1] = 0;  // integers(0,1): rng==0, no draw consumed
        for (int i = 2; i < N_; i++) {
            uint32_t rng = (uint32_t)i - 1u;
            uint32_t rng_excl = rng + 1u;
            uint64_t m;
            uint32_t leftover;
            for (;;) {
                uint32_t r32;
                if (has32) {
                    has32 = 0;
                    r32 = cached;
                } else {
                    state = state * MULT + inc;
                    uint64_t hi = (uint64_t)(state >> 64);
                    uint64_t lo = (uint64_t)state;
                    unsigned rot = (unsigned)(uint64_t)(state >> 122);
                    uint64_t x = hi ^ lo;
                    uint64_t o = (x >> rot) | (x << ((64u - rot) & 63u));
                    has32 = 1;
                    cached = (uint32_t)(o >> 32);
                    r32 = (uint32_t)o;
                }
                m = (uint64_t)r32 * (uint64_t)rng_excl;
                leftover = (uint32_t)m;
                if (leftover >= rng_excl) break;
                uint32_t thr = (0xFFFFFFFFu - rng) % rng_excl;
                if (leftover >= thr) break;
            }
            f->par[t][i] = (int)(uint32_t)(m >> 32);
        }
    }
}

extern "C" void kernel_launch(void* const* d_in, const int* in_sizes, int n_in,
                              void* d_out, int out_size) {
    const float* x = (const float*)d_in[0];
    const float* alphas = (const float*)d_in[1];
    float* out = (float*)d_out;

    Forest f;
    compute_forest(&f);

    xv_kernel<<<NTOT / 4 / 256, 256>>>(x);
    forest_kernel<<<B_ * C_ * T_, 32>>>(alphas, out, f);
}